// round 2
// baseline (speedup 1.0000x reference)
#include <cuda_runtime.h>
#include <cuda_bf16.h>

#define THREADS 256
#define MAX_EDGES 100000

// Precomputed edge contributions: PE[e][0:64] = E[e] @ W1^T, PE[e][64:128] = E[e] @ W2^T
__device__ float g_PE[MAX_EDGES * 128];

// ---------------------------------------------------------------------------
// Kernel A: PE[e][c] = sum_k HE[e][k] * W[c<64 ? c : c-64][ (c<64?0:64) + k ]
// 100k x 64 @ 64 x 128 GEMM. 32 edge rows per block.
// ---------------------------------------------------------------------------
__global__ __launch_bounds__(THREADS) void edge_precompute(
    const float* __restrict__ HE, const float* __restrict__ W, int n_edges)
{
    __shared__ float WA[64 * 132];   // WA[k*132 + c], padded rows (132*4B = 16B-aligned)
    __shared__ float Xs[32 * 64];

    // Stage W-derived table: coalesced global reads, strided STS (one-time cost)
    for (int i = threadIdx.x; i < 64 * 128; i += THREADS) {
        int c = i >> 6;          // 0..127 (output column)
        int k = i & 63;          // contraction index (fastest -> coalesced)
        float v = (c < 64) ? W[c * 192 + k] : W[(c - 64) * 192 + 64 + k];
        WA[k * 132 + c] = v;
    }

    int e0 = blockIdx.x * 32;
    int valid_rows = n_edges - e0; if (valid_rows > 32) valid_rows = 32;

    const float4* src = reinterpret_cast<const float4*>(HE + (size_t)e0 * 64);
    float4* Xs4 = reinterpret_cast<float4*>(Xs);
    for (int i = threadIdx.x; i < valid_rows * 16; i += THREADS)
        Xs4[i] = src[i];
    __syncthreads();

    int lane = threadIdx.x & 31;
    int warp = threadIdx.x >> 5;
    int c4 = lane * 4;           // each lane owns 4 output columns

    #pragma unroll
    for (int rg = 0; rg < 4; rg++) {
        int row = rg * 8 + warp;
        if (row < valid_rows) {
            float a0 = 0.f, a1 = 0.f, a2 = 0.f, a3 = 0.f;
            #pragma unroll
            for (int kq = 0; kq < 16; kq++) {
                float4 xv = Xs4[row * 16 + kq];
                const float* wr = &WA[(kq * 4) * 132 + c4];
                float4 w0 = *reinterpret_cast<const float4*>(wr);
                float4 w1 = *reinterpret_cast<const float4*>(wr + 132);
                float4 w2 = *reinterpret_cast<const float4*>(wr + 264);
                float4 w3 = *reinterpret_cast<const float4*>(wr + 396);
                a0 = fmaf(xv.x, w0.x, a0); a1 = fmaf(xv.x, w0.y, a1);
                a2 = fmaf(xv.x, w0.z, a2); a3 = fmaf(xv.x, w0.w, a3);
                a0 = fmaf(xv.y, w1.x, a0); a1 = fmaf(xv.y, w1.y, a1);
                a2 = fmaf(xv.y, w1.z, a2); a3 = fmaf(xv.y, w1.w, a3);
                a0 = fmaf(xv.z, w2.x, a0); a1 = fmaf(xv.z, w2.y, a1);
                a2 = fmaf(xv.z, w2.z, a2); a3 = fmaf(xv.z, w2.w, a3);
                a0 = fmaf(xv.w, w3.x, a0); a1 = fmaf(xv.w, w3.y, a1);
                a2 = fmaf(xv.w, w3.z, a2); a3 = fmaf(xv.w, w3.w, a3);
            }
            float4 r; r.x = a0; r.y = a1; r.z = a2; r.w = a3;
            *reinterpret_cast<float4*>(&g_PE[(size_t)(e0 + row) * 128 + c4]) = r;
        }
    }
}

// ---------------------------------------------------------------------------
// Kernel B: out[i][o] = relu( PE[a0[i]][o] + PE[a1[i]][64+o]
//                             + sum_k X[i][k]*W[o][128+k] + b[o] )
// 32 incidence rows per tile; grid-stride over tiles; W staged once per block.
// aff is INT32 (JAX default config demotes int64 -> int32).
// ---------------------------------------------------------------------------
__global__ __launch_bounds__(THREADS) void e2v_fused(
    const float* __restrict__ node, const int* __restrict__ aff,
    const float* __restrict__ W, const float* __restrict__ bias,
    float* __restrict__ out, int n_inc, int n_edges)
{
    __shared__ float Ws[64 * 68];    // Ws[k*68 + o], padded (68*4B = 16B-aligned)
    __shared__ float Xs[32 * 64];

    for (int i = threadIdx.x; i < 64 * 64; i += THREADS) {
        int o = i >> 6;
        int k = i & 63;              // k fastest -> coalesced global read
        Ws[k * 68 + o] = W[o * 192 + 128 + k];
    }

    int tidx = threadIdx.x;
    int ocol = (tidx & 15) * 4;      // 4 output columns per thread
    int rsub = tidx >> 4;            // 0..15 (row within half-tile)
    float4 bv = *reinterpret_cast<const float4*>(bias + ocol);

    float4* Xs4 = reinterpret_cast<float4*>(Xs);
    const float4* PE4 = reinterpret_cast<const float4*>(g_PE);

    int n_tiles = (n_inc + 31) >> 5;
    for (int t = blockIdx.x; t < n_tiles; t += gridDim.x) {
        __syncthreads();             // protect Xs reuse (also orders Ws on iter 0)
        int r0 = t * 32;
        int vr = n_inc - r0; if (vr > 32) vr = 32;
        const float4* src = reinterpret_cast<const float4*>(node + (size_t)r0 * 64);
        for (int i = tidx; i < vr * 16; i += THREADS)
            Xs4[i] = src[i];
        __syncthreads();

        #pragma unroll
        for (int p = 0; p < 2; p++) {
            int row = p * 16 + rsub;
            int gi = r0 + row;
            if (gi < n_inc) {
                float a0 = bv.x, a1 = bv.y, a2 = bv.z, a3 = bv.w;
                #pragma unroll
                for (int kq = 0; kq < 16; kq++) {
                    float4 xv = Xs4[row * 16 + kq];
                    const float* wr = &Ws[(kq * 4) * 68 + ocol];
                    float4 w0 = *reinterpret_cast<const float4*>(wr);
                    float4 w1 = *reinterpret_cast<const float4*>(wr + 68);
                    float4 w2 = *reinterpret_cast<const float4*>(wr + 136);
                    float4 w3 = *reinterpret_cast<const float4*>(wr + 204);
                    a0 = fmaf(xv.x, w0.x, a0); a1 = fmaf(xv.x, w0.y, a1);
                    a2 = fmaf(xv.x, w0.z, a2); a3 = fmaf(xv.x, w0.w, a3);
                    a0 = fmaf(xv.y, w1.x, a0); a1 = fmaf(xv.y, w1.y, a1);
                    a2 = fmaf(xv.y, w1.z, a2); a3 = fmaf(xv.y, w1.w, a3);
                    a0 = fmaf(xv.z, w2.x, a0); a1 = fmaf(xv.z, w2.y, a1);
                    a2 = fmaf(xv.z, w2.z, a2); a3 = fmaf(xv.z, w2.w, a3);
                    a0 = fmaf(xv.w, w3.x, a0); a1 = fmaf(xv.w, w3.y, a1);
                    a2 = fmaf(xv.w, w3.z, a2); a3 = fmaf(xv.w, w3.w, a3);
                }
                int e0 = aff[gi];
                int e1 = aff[(size_t)n_inc + gi];
                // defensive clamp: OOB dtype surprises become rel_err, not err715
                e0 = min(max(e0, 0), n_edges - 1);
                e1 = min(max(e1, 0), n_edges - 1);
                float4 p0 = PE4[(size_t)e0 * 32 + (ocol >> 2)];
                float4 p1 = PE4[(size_t)e1 * 32 + 16 + (ocol >> 2)];
                a0 += p0.x + p1.x;
                a1 += p0.y + p1.y;
                a2 += p0.z + p1.z;
                a3 += p0.w + p1.w;
                float4 r;
                r.x = a0 > 0.f ? a0 : 0.f;
                r.y = a1 > 0.f ? a1 : 0.f;
                r.z = a2 > 0.f ? a2 : 0.f;
                r.w = a3 > 0.f ? a3 : 0.f;
                *reinterpret_cast<float4*>(&out[(size_t)gi * 64 + ocol]) = r;
            }
        }
    }
}

extern "C" void kernel_launch(void* const* d_in, const int* in_sizes, int n_in,
                              void* d_out, int out_size) {
    const float* HE   = (const float*)d_in[0];      // [N_EDGES, 64]
    const float* node = (const float*)d_in[1];      // [N_INC, 64]
    const int*   aff  = (const int*)d_in[2];        // [2, N_INC] int32 (JAX default)
    const float* W    = (const float*)d_in[3];      // [64, 192]
    const float* bias = (const float*)d_in[4];      // [64]
    float* out = (float*)d_out;

    int n_edges = in_sizes[0] / 64;
    int n_inc   = in_sizes[1] / 64;
    if (n_edges > MAX_EDGES) n_edges = MAX_EDGES;

    int grid_a = (n_edges + 31) / 32;
    edge_precompute<<<grid_a, THREADS>>>(HE, W, n_edges);

    int n_tiles = (n_inc + 31) / 32;
    int grid_b = n_tiles < 2048 ? n_tiles : 2048;
    e2v_fused<<<grid_b, THREADS>>>(node, aff, W, bias, out, n_inc, n_edges);
}

// round 3
// speedup vs baseline: 1.9934x; 1.9934x over previous
#include <cuda_runtime.h>
#include <cuda_bf16.h>

#define THREADS 256
#define MAX_EDGES 100000
#define TILE_R 256           // rows per block tile (kernel B)
#define XS_STRIDE 65         // padded row stride for Xs (conflict-free column reads)

// Precomputed edge contributions: PE[e][0:64] = E[e]@W1^T, PE[e][64:128] = E[e]@W2^T
__device__ float g_PE[MAX_EDGES * 128];

// ---------------------------------------------------------------------------
// Kernel A: edge precompute (100k x 64 @ 64 x 128). Small (1/20 of B's work).
// ---------------------------------------------------------------------------
__global__ __launch_bounds__(THREADS) void edge_precompute(
    const float* __restrict__ HE, const float* __restrict__ W, int n_edges)
{
    __shared__ float WA[64 * 132];
    __shared__ float Xs[32 * 64];

    for (int i = threadIdx.x; i < 64 * 128; i += THREADS) {
        int c = i >> 6;
        int k = i & 63;
        float v = (c < 64) ? W[c * 192 + k] : W[(c - 64) * 192 + 64 + k];
        WA[k * 132 + c] = v;
    }

    int e0 = blockIdx.x * 32;
    int valid_rows = n_edges - e0; if (valid_rows > 32) valid_rows = 32;

    const float4* src = reinterpret_cast<const float4*>(HE + (size_t)e0 * 64);
    float4* Xs4 = reinterpret_cast<float4*>(Xs);
    for (int i = threadIdx.x; i < valid_rows * 16; i += THREADS)
        Xs4[i] = src[i];
    __syncthreads();

    int lane = threadIdx.x & 31;
    int warp = threadIdx.x >> 5;
    int c4 = lane * 4;

    #pragma unroll
    for (int rg = 0; rg < 4; rg++) {
        int row = rg * 8 + warp;
        if (row < valid_rows) {
            float a0 = 0.f, a1 = 0.f, a2 = 0.f, a3 = 0.f;
            #pragma unroll
            for (int kq = 0; kq < 16; kq++) {
                float4 xv = Xs4[row * 16 + kq];
                const float* wr = &WA[(kq * 4) * 132 + c4];
                float4 w0 = *reinterpret_cast<const float4*>(wr);
                float4 w1 = *reinterpret_cast<const float4*>(wr + 132);
                float4 w2 = *reinterpret_cast<const float4*>(wr + 264);
                float4 w3 = *reinterpret_cast<const float4*>(wr + 396);
                a0 = fmaf(xv.x, w0.x, a0); a1 = fmaf(xv.x, w0.y, a1);
                a2 = fmaf(xv.x, w0.z, a2); a3 = fmaf(xv.x, w0.w, a3);
                a0 = fmaf(xv.y, w1.x, a0); a1 = fmaf(xv.y, w1.y, a1);
                a2 = fmaf(xv.y, w1.z, a2); a3 = fmaf(xv.y, w1.w, a3);
                a0 = fmaf(xv.z, w2.x, a0); a1 = fmaf(xv.z, w2.y, a1);
                a2 = fmaf(xv.z, w2.z, a2); a3 = fmaf(xv.z, w2.w, a3);
                a0 = fmaf(xv.w, w3.x, a0); a1 = fmaf(xv.w, w3.y, a1);
                a2 = fmaf(xv.w, w3.z, a2); a3 = fmaf(xv.w, w3.w, a3);
            }
            float4 r; r.x = a0; r.y = a1; r.z = a2; r.w = a3;
            *reinterpret_cast<float4*>(&g_PE[(size_t)(e0 + row) * 128 + c4]) = r;
        }
    }
}

// ---------------------------------------------------------------------------
// Kernel B v2: register-tiled (8 rows x 8 cols / thread), packed f32x2 FMA.
//   out[i][o] = relu( PE[a0[i]][o] + PE[a1[i]][64+o] + X[i]@W3^T[o] + b[o] )
// Tile: 256 rows x 64 cols, 256 threads, grid-stride, W staged once.
// smem: Ws[64][64] (k-major rows, col-fast)  +  Xs[256][65] (row-major, padded)
// ---------------------------------------------------------------------------
__global__ __launch_bounds__(THREADS, 2) void e2v_fused_v2(
    const float* __restrict__ node, const int* __restrict__ aff,
    const float* __restrict__ W, const float* __restrict__ bias,
    float* __restrict__ out, int n_inc, int n_edges)
{
    extern __shared__ float smem[];
    float* Ws = smem;                         // 64*64 floats
    float* Xs = smem + 64 * 64;               // 256*65 floats

    int tid = threadIdx.x;
    int cx  = tid & 7;     // col group: cols cx*8 .. cx*8+7
    int ry  = tid >> 3;    // row group: rows ry*8 .. ry*8+7

    // Stage W3 (k-major, col-fast). Coalesced global; one-time STS conflicts OK.
    for (int i = tid; i < 64 * 64; i += THREADS) {
        int k = i & 63;
        int o = i >> 6;
        Ws[k * 64 + o] = W[o * 192 + 128 + k];
    }

    // Bias as 4 packed f32x2 column-pairs for this thread's 8 cols.
    float4 b0 = *reinterpret_cast<const float4*>(bias + cx * 8);
    float4 b1 = *reinterpret_cast<const float4*>(bias + cx * 8 + 4);
    unsigned long long binit[4];
    asm("mov.b64 %0, {%1, %2};" : "=l"(binit[0]) : "f"(b0.x), "f"(b0.y));
    asm("mov.b64 %0, {%1, %2};" : "=l"(binit[1]) : "f"(b0.z), "f"(b0.w));
    asm("mov.b64 %0, {%1, %2};" : "=l"(binit[2]) : "f"(b1.x), "f"(b1.y));
    asm("mov.b64 %0, {%1, %2};" : "=l"(binit[3]) : "f"(b1.z), "f"(b1.w));

    const float4* node4 = reinterpret_cast<const float4*>(node);
    const float4* PE4   = reinterpret_cast<const float4*>(g_PE);

    int n_tiles = (n_inc + TILE_R - 1) / TILE_R;
    for (int t = blockIdx.x; t < n_tiles; t += gridDim.x) {
        __syncthreads();   // previous tile's Xs readers done (also orders Ws once)
        int r0 = t * TILE_R;
        int vr = n_inc - r0; if (vr > TILE_R) vr = TILE_R;

        // Fill Xs: coalesced float4 loads, scalar padded stores (2-way conflict).
        #pragma unroll
        for (int it = 0; it < (TILE_R * 16) / THREADS; it++) {
            int i = tid + it * THREADS;
            int r = i >> 4, kq = i & 15;
            float4 v = make_float4(0.f, 0.f, 0.f, 0.f);
            if (r < vr) v = node4[(size_t)(r0 + r) * 16 + kq];
            float* dst = &Xs[r * XS_STRIDE + kq * 4];
            dst[0] = v.x; dst[1] = v.y; dst[2] = v.z; dst[3] = v.w;
        }
        __syncthreads();

        // Accumulators: 8 rows x 4 col-pairs (f32x2), bias-initialized.
        unsigned long long acc[8][4];
        #pragma unroll
        for (int j = 0; j < 8; j++) {
            acc[j][0] = binit[0]; acc[j][1] = binit[1];
            acc[j][2] = binit[2]; acc[j][3] = binit[3];
        }

        // Main GEMM loop over k. W col-pairs load naturally as f32x2.
        #pragma unroll 8
        for (int k = 0; k < 64; k++) {
            const float* wrow = &Ws[k * 64 + cx * 8];
            unsigned long long w0, w1, w2, w3;
            {
                ulonglong2 wA = *reinterpret_cast<const ulonglong2*>(wrow);
                ulonglong2 wB = *reinterpret_cast<const ulonglong2*>(wrow + 4);
                w0 = wA.x; w1 = wA.y; w2 = wB.x; w3 = wB.y;
            }
            const float* xcol = &Xs[(ry * 8) * XS_STRIDE + k];
            #pragma unroll
            for (int j = 0; j < 8; j++) {
                float xv = xcol[j * XS_STRIDE];
                unsigned long long xd;
                asm("mov.b64 %0, {%1, %1};" : "=l"(xd) : "f"(xv));
                asm("fma.rn.f32x2 %0, %1, %2, %0;" : "+l"(acc[j][0]) : "l"(xd), "l"(w0));
                asm("fma.rn.f32x2 %0, %1, %2, %0;" : "+l"(acc[j][1]) : "l"(xd), "l"(w1));
                asm("fma.rn.f32x2 %0, %1, %2, %0;" : "+l"(acc[j][2]) : "l"(xd), "l"(w2));
                asm("fma.rn.f32x2 %0, %1, %2, %0;" : "+l"(acc[j][3]) : "l"(xd), "l"(w3));
            }
        }

        // Epilogue: gather PE, add, relu, store.
        #pragma unroll
        for (int j = 0; j < 8; j++) {
            int gi = r0 + ry * 8 + j;
            if (gi < n_inc) {
                int e0 = aff[gi];
                int e1 = aff[(size_t)n_inc + gi];
                e0 = min(max(e0, 0), n_edges - 1);
                e1 = min(max(e1, 0), n_edges - 1);
                float4 p0a = PE4[(size_t)e0 * 32 + cx * 2];
                float4 p0b = PE4[(size_t)e0 * 32 + cx * 2 + 1];
                float4 p1a = PE4[(size_t)e1 * 32 + 16 + cx * 2];
                float4 p1b = PE4[(size_t)e1 * 32 + 16 + cx * 2 + 1];
                float f[8];
                asm("mov.b64 {%0, %1}, %2;" : "=f"(f[0]), "=f"(f[1]) : "l"(acc[j][0]));
                asm("mov.b64 {%0, %1}, %2;" : "=f"(f[2]), "=f"(f[3]) : "l"(acc[j][1]));
                asm("mov.b64 {%0, %1}, %2;" : "=f"(f[4]), "=f"(f[5]) : "l"(acc[j][2]));
                asm("mov.b64 {%0, %1}, %2;" : "=f"(f[6]), "=f"(f[7]) : "l"(acc[j][3]));
                float4 ra, rb;
                ra.x = f[0] + p0a.x + p1a.x;  ra.y = f[1] + p0a.y + p1a.y;
                ra.z = f[2] + p0a.z + p1a.z;  ra.w = f[3] + p0a.w + p1a.w;
                rb.x = f[4] + p0b.x + p1b.x;  rb.y = f[5] + p0b.y + p1b.y;
                rb.z = f[6] + p0b.z + p1b.z;  rb.w = f[7] + p0b.w + p1b.w;
                ra.x = ra.x > 0.f ? ra.x : 0.f;  ra.y = ra.y > 0.f ? ra.y : 0.f;
                ra.z = ra.z > 0.f ? ra.z : 0.f;  ra.w = ra.w > 0.f ? ra.w : 0.f;
                rb.x = rb.x > 0.f ? rb.x : 0.f;  rb.y = rb.y > 0.f ? rb.y : 0.f;
                rb.z = rb.z > 0.f ? rb.z : 0.f;  rb.w = rb.w > 0.f ? rb.w : 0.f;
                float* orow = out + (size_t)gi * 64 + cx * 8;
                *reinterpret_cast<float4*>(orow)     = ra;
                *reinterpret_cast<float4*>(orow + 4) = rb;
            }
        }
    }
}

extern "C" void kernel_launch(void* const* d_in, const int* in_sizes, int n_in,
                              void* d_out, int out_size) {
    const float* HE   = (const float*)d_in[0];      // [N_EDGES, 64]
    const float* node = (const float*)d_in[1];      // [N_INC, 64]
    const int*   aff  = (const int*)d_in[2];        // [2, N_INC] int32
    const float* W    = (const float*)d_in[3];      // [64, 192]
    const float* bias = (const float*)d_in[4];      // [64]
    float* out = (float*)d_out;

    int n_edges = in_sizes[0] / 64;
    int n_inc   = in_sizes[1] / 64;
    if (n_edges > MAX_EDGES) n_edges = MAX_EDGES;

    int grid_a = (n_edges + 31) / 32;
    edge_precompute<<<grid_a, THREADS>>>(HE, W, n_edges);

    size_t smem_b = (size_t)(64 * 64 + TILE_R * XS_STRIDE) * sizeof(float);  // ~83 KB
    cudaFuncSetAttribute(e2v_fused_v2, cudaFuncAttributeMaxDynamicSharedMemorySize,
                         (int)smem_b);

    int n_tiles = (n_inc + TILE_R - 1) / TILE_R;
    int grid_b = n_tiles < 296 ? n_tiles : 296;     // 148 SMs x 2 CTAs
    e2v_fused_v2<<<grid_b, THREADS, smem_b>>>(node, aff, W, bias, out, n_inc, n_edges);
}

// round 4
// speedup vs baseline: 2.0199x; 1.0133x over previous
#include <cuda_runtime.h>
#include <cuda_bf16.h>

#define THREADS 256
#define MAX_EDGES 100000
#define TILE_R 256
#define XS_STRIDE 68         // %4==0 (aligned float4 rows), rows 1 apart -> bank offset 4

// Precomputed edge contributions: PE[e][0:64] = E[e]@W1^T, PE[e][64:128] = E[e]@W2^T
__device__ float g_PE[MAX_EDGES * 128];

// ---------------------------------------------------------------------------
// Kernel A: edge precompute. Tile 128 rows x 128 cols, 256 threads,
// 8x8 per thread, f32x2 FMA. Warps 0-3: cols 0-63, warps 4-7: cols 64-127.
// smem: WsA/WsB[64][64] (even/odd col-quads) + Xs[128][68]
// ---------------------------------------------------------------------------
__global__ __launch_bounds__(THREADS, 2) void edge_precompute_v2(
    const float* __restrict__ HE, const float* __restrict__ W, int n_edges)
{
    extern __shared__ float sm[];
    float* WsA = sm;                    // 64*64
    float* WsB = sm + 64 * 64;          // 64*64
    float* Xs  = sm + 2 * 64 * 64;      // 128*68

    int tid  = threadIdx.x;
    int lane = tid & 31;
    int warp = tid >> 5;
    int rw   = lane & 3;
    int cx   = lane >> 2;               // 0..7
    int colhalf = warp >> 2;            // 0 or 1
    int rowbase = (warp & 3) * 32 + rw; // rows rowbase + 4j

    // Stage combined W1|W2 table, split even/odd col-quads.
    for (int i = tid; i < 64 * 128; i += THREADS) {
        int o = i >> 6;                 // 0..127
        int k = i & 63;                 // coalesced
        float v = (o < 64) ? W[o * 192 + k] : W[(o - 64) * 192 + 64 + k];
        int q = o >> 2;
        float* dst = (q & 1) ? WsB : WsA;
        dst[k * 64 + (q >> 1) * 4 + (o & 3)] = v;
    }

    int e0 = blockIdx.x * 128;
    int vr = n_edges - e0; if (vr > 128) vr = 128;

    const float4* src = reinterpret_cast<const float4*>(HE);
    #pragma unroll
    for (int it = 0; it < 8; it++) {
        int i = tid + it * THREADS;
        int r = i >> 4, kq = i & 15;
        float4 v = make_float4(0.f, 0.f, 0.f, 0.f);
        if (r < vr) v = src[(size_t)(e0 + r) * 16 + kq];
        *reinterpret_cast<float4*>(&Xs[r * XS_STRIDE + kq * 4]) = v;
    }
    __syncthreads();

    unsigned long long acc[8][4];
    #pragma unroll
    for (int j = 0; j < 8; j++) { acc[j][0]=0; acc[j][1]=0; acc[j][2]=0; acc[j][3]=0; }

    #pragma unroll 4
    for (int kq = 0; kq < 16; kq++) {
        float4 xv[8];
        #pragma unroll
        for (int j = 0; j < 8; j++)
            xv[j] = *reinterpret_cast<const float4*>(&Xs[(rowbase + 4 * j) * XS_STRIDE + kq * 4]);
        #pragma unroll
        for (int kk = 0; kk < 4; kk++) {
            int k = kq * 4 + kk;
            ulonglong2 wA = *reinterpret_cast<const ulonglong2*>(&WsA[k * 64 + colhalf * 32 + cx * 4]);
            ulonglong2 wB = *reinterpret_cast<const ulonglong2*>(&WsB[k * 64 + colhalf * 32 + cx * 4]);
            #pragma unroll
            for (int j = 0; j < 8; j++) {
                float x = reinterpret_cast<const float*>(&xv[j])[kk];
                unsigned long long xd;
                asm("mov.b64 %0, {%1, %1};" : "=l"(xd) : "f"(x));
                asm("fma.rn.f32x2 %0, %1, %2, %0;" : "+l"(acc[j][0]) : "l"(xd), "l"(wA.x));
                asm("fma.rn.f32x2 %0, %1, %2, %0;" : "+l"(acc[j][1]) : "l"(wA.y), "l"(xd));
                asm("fma.rn.f32x2 %0, %1, %2, %0;" : "+l"(acc[j][2]) : "l"(xd), "l"(wB.x));
                asm("fma.rn.f32x2 %0, %1, %2, %0;" : "+l"(acc[j][3]) : "l"(wB.y), "l"(xd));
            }
        }
    }

    #pragma unroll
    for (int j = 0; j < 8; j++) {
        int row = rowbase + 4 * j;
        if (row < vr) {
            float f[8];
            asm("mov.b64 {%0, %1}, %2;" : "=f"(f[0]), "=f"(f[1]) : "l"(acc[j][0]));
            asm("mov.b64 {%0, %1}, %2;" : "=f"(f[2]), "=f"(f[3]) : "l"(acc[j][1]));
            asm("mov.b64 {%0, %1}, %2;" : "=f"(f[4]), "=f"(f[5]) : "l"(acc[j][2]));
            asm("mov.b64 {%0, %1}, %2;" : "=f"(f[6]), "=f"(f[7]) : "l"(acc[j][3]));
            float* orow = &g_PE[(size_t)(e0 + row) * 128 + colhalf * 64 + cx * 8];
            *reinterpret_cast<float4*>(orow)     = make_float4(f[0], f[1], f[2], f[3]);
            *reinterpret_cast<float4*>(orow + 4) = make_float4(f[4], f[5], f[6], f[7]);
        }
    }
}

// ---------------------------------------------------------------------------
// Kernel B v3: tile 256 rows x 64 cols, 8x8 per thread, f32x2, vectorized
// x loads, conflict-free W via even/odd quad split.
// smem: WsA/WsB[64][32] + Xs[256][68]
// ---------------------------------------------------------------------------
__global__ __launch_bounds__(THREADS, 2) void e2v_fused_v3(
    const float* __restrict__ node, const int* __restrict__ aff,
    const float* __restrict__ W, const float* __restrict__ bias,
    float* __restrict__ out, int n_inc, int n_edges)
{
    extern __shared__ float sm[];
    float* WsA = sm;                    // 64*32
    float* WsB = sm + 64 * 32;          // 64*32
    float* Xs  = sm + 2 * 64 * 32;      // 256*68

    int tid  = threadIdx.x;
    int lane = tid & 31;
    int warp = tid >> 5;
    int rw   = lane & 3;
    int cx   = lane >> 2;               // 0..7, cols cx*8..cx*8+7
    int rowbase = warp * 32 + rw;       // rows rowbase + 4j within tile

    // Stage W3, split even/odd col-quads.
    for (int i = tid; i < 64 * 64; i += THREADS) {
        int o = i >> 6;
        int k = i & 63;                 // coalesced
        float v = W[o * 192 + 128 + k];
        int q = o >> 2;
        float* dst = (q & 1) ? WsB : WsA;
        dst[k * 32 + (q >> 1) * 4 + (o & 3)] = v;
    }

    float4 b0 = *reinterpret_cast<const float4*>(bias + cx * 8);
    float4 b1 = *reinterpret_cast<const float4*>(bias + cx * 8 + 4);
    unsigned long long binit[4];
    asm("mov.b64 %0, {%1, %2};" : "=l"(binit[0]) : "f"(b0.x), "f"(b0.y));
    asm("mov.b64 %0, {%1, %2};" : "=l"(binit[1]) : "f"(b0.z), "f"(b0.w));
    asm("mov.b64 %0, {%1, %2};" : "=l"(binit[2]) : "f"(b1.x), "f"(b1.y));
    asm("mov.b64 %0, {%1, %2};" : "=l"(binit[3]) : "f"(b1.z), "f"(b1.w));

    const float4* node4 = reinterpret_cast<const float4*>(node);
    const float4* PE4   = reinterpret_cast<const float4*>(g_PE);

    int n_tiles = (n_inc + TILE_R - 1) / TILE_R;
    for (int t = blockIdx.x; t < n_tiles; t += gridDim.x) {
        __syncthreads();
        int r0 = t * TILE_R;
        int vr = n_inc - r0; if (vr > TILE_R) vr = TILE_R;

        #pragma unroll
        for (int it = 0; it < (TILE_R * 16) / THREADS; it++) {
            int i = tid + it * THREADS;
            int r = i >> 4, kq = i & 15;
            float4 v = make_float4(0.f, 0.f, 0.f, 0.f);
            if (r < vr) v = node4[(size_t)(r0 + r) * 16 + kq];
            *reinterpret_cast<float4*>(&Xs[r * XS_STRIDE + kq * 4]) = v;
        }
        __syncthreads();

        unsigned long long acc[8][4];
        #pragma unroll
        for (int j = 0; j < 8; j++) {
            acc[j][0] = binit[0]; acc[j][1] = binit[1];
            acc[j][2] = binit[2]; acc[j][3] = binit[3];
        }

        #pragma unroll 4
        for (int kq = 0; kq < 16; kq++) {
            float4 xv[8];
            #pragma unroll
            for (int j = 0; j < 8; j++)
                xv[j] = *reinterpret_cast<const float4*>(&Xs[(rowbase + 4 * j) * XS_STRIDE + kq * 4]);
            #pragma unroll
            for (int kk = 0; kk < 4; kk++) {
                int k = kq * 4 + kk;
                ulonglong2 wA = *reinterpret_cast<const ulonglong2*>(&WsA[k * 32 + cx * 4]);
                ulonglong2 wB = *reinterpret_cast<const ulonglong2*>(&WsB[k * 32 + cx * 4]);
                #pragma unroll
                for (int j = 0; j < 8; j++) {
                    float x = reinterpret_cast<const float*>(&xv[j])[kk];
                    unsigned long long xd;
                    asm("mov.b64 %0, {%1, %1};" : "=l"(xd) : "f"(x));
                    asm("fma.rn.f32x2 %0, %1, %2, %0;" : "+l"(acc[j][0]) : "l"(xd), "l"(wA.x));
                    asm("fma.rn.f32x2 %0, %1, %2, %0;" : "+l"(acc[j][1]) : "l"(wA.y), "l"(xd));
                    asm("fma.rn.f32x2 %0, %1, %2, %0;" : "+l"(acc[j][2]) : "l"(xd), "l"(wB.x));
                    asm("fma.rn.f32x2 %0, %1, %2, %0;" : "+l"(acc[j][3]) : "l"(wB.y), "l"(xd));
                }
            }
        }

        #pragma unroll
        for (int j = 0; j < 8; j++) {
            int gi = r0 + rowbase + 4 * j;
            if (gi < n_inc) {
                int e0 = aff[gi];
                int e1 = aff[(size_t)n_inc + gi];
                e0 = min(max(e0, 0), n_edges - 1);
                e1 = min(max(e1, 0), n_edges - 1);
                float4 p0a = PE4[(size_t)e0 * 32 + cx * 2];
                float4 p0b = PE4[(size_t)e0 * 32 + cx * 2 + 1];
                float4 p1a = PE4[(size_t)e1 * 32 + 16 + cx * 2];
                float4 p1b = PE4[(size_t)e1 * 32 + 16 + cx * 2 + 1];
                float f[8];
                asm("mov.b64 {%0, %1}, %2;" : "=f"(f[0]), "=f"(f[1]) : "l"(acc[j][0]));
                asm("mov.b64 {%0, %1}, %2;" : "=f"(f[2]), "=f"(f[3]) : "l"(acc[j][1]));
                asm("mov.b64 {%0, %1}, %2;" : "=f"(f[4]), "=f"(f[5]) : "l"(acc[j][2]));
                asm("mov.b64 {%0, %1}, %2;" : "=f"(f[6]), "=f"(f[7]) : "l"(acc[j][3]));
                float4 ra, rb;
                ra.x = f[0] + p0a.x + p1a.x;  ra.y = f[1] + p0a.y + p1a.y;
                ra.z = f[2] + p0a.z + p1a.z;  ra.w = f[3] + p0a.w + p1a.w;
                rb.x = f[4] + p0b.x + p1b.x;  rb.y = f[5] + p0b.y + p1b.y;
                rb.z = f[6] + p0b.z + p1b.z;  rb.w = f[7] + p0b.w + p1b.w;
                ra.x = ra.x > 0.f ? ra.x : 0.f;  ra.y = ra.y > 0.f ? ra.y : 0.f;
                ra.z = ra.z > 0.f ? ra.z : 0.f;  ra.w = ra.w > 0.f ? ra.w : 0.f;
                rb.x = rb.x > 0.f ? rb.x : 0.f;  rb.y = rb.y > 0.f ? rb.y : 0.f;
                rb.z = rb.z > 0.f ? rb.z : 0.f;  rb.w = rb.w > 0.f ? rb.w : 0.f;
                float* orow = out + (size_t)gi * 64 + cx * 8;
                *reinterpret_cast<float4*>(orow)     = ra;
                *reinterpret_cast<float4*>(orow + 4) = rb;
            }
        }
    }
}

extern "C" void kernel_launch(void* const* d_in, const int* in_sizes, int n_in,
                              void* d_out, int out_size) {
    const float* HE   = (const float*)d_in[0];      // [N_EDGES, 64]
    const float* node = (const float*)d_in[1];      // [N_INC, 64]
    const int*   aff  = (const int*)d_in[2];        // [2, N_INC] int32
    const float* W    = (const float*)d_in[3];      // [64, 192]
    const float* bias = (const float*)d_in[4];      // [64]
    float* out = (float*)d_out;

    int n_edges = in_sizes[0] / 64;
    int n_inc   = in_sizes[1] / 64;
    if (n_edges > MAX_EDGES) n_edges = MAX_EDGES;

    size_t smem_a = (size_t)(2 * 64 * 64 + 128 * XS_STRIDE) * sizeof(float);   // ~67 KB
    size_t smem_b = (size_t)(2 * 64 * 32 + TILE_R * XS_STRIDE) * sizeof(float); // ~84 KB
    cudaFuncSetAttribute(edge_precompute_v2, cudaFuncAttributeMaxDynamicSharedMemorySize, (int)smem_a);
    cudaFuncSetAttribute(e2v_fused_v3, cudaFuncAttributeMaxDynamicSharedMemorySize, (int)smem_b);

    int grid_a = (n_edges + 127) / 128;
    edge_precompute_v2<<<grid_a, THREADS, smem_a>>>(HE, W, n_edges);

    int n_tiles = (n_inc + TILE_R - 1) / TILE_R;
    int grid_b = n_tiles < 296 ? n_tiles : 296;     // 148 SMs x 2 CTAs
    e2v_fused_v3<<<grid_b, THREADS, smem_b>>>(node, aff, W, bias, out, n_inc, n_edges);
}